// round 1
// baseline (speedup 1.0000x reference)
#include <cuda_runtime.h>
#include <math.h>

// Problem dims (fixed by the reference setup_inputs)
#define BB   2
#define NN   1024
#define HH   8
#define GG   8
#define HG   64            // H*G
#define NBATCH (BB*HG)     // 128 independent GEMM batches
#define NROWS  (BB*NN*HG)  // 131072 SH rows per side
#define DPAD 16            // 15 SH components padded to 16 for float4

// Scratch: Y_q / Y_k in [B, H, G, N, 16] layout (batch-major, row n, padded d)
__device__ float g_Yq[(size_t)NBATCH * NN * DPAD];
__device__ float g_Yk[(size_t)NBATCH * NN * DPAD];

// ---------------------------------------------------------------------------
// Kernel 1: rotate -> normalize -> spherical harmonics (l=1,2,3, e3nn order)
// One thread per (b,n,h,g). "scale" folds the final 1/sqrt(15) into Y_q.
// ---------------------------------------------------------------------------
__global__ void sh_expand_kernel(const float* __restrict__ v_in,
                                 const float* __restrict__ r_in,
                                 float scale, int which)
{
    int t = blockIdx.x * blockDim.x + threadIdx.x;
    if (t >= NROWS) return;

    int hg = t & (HG - 1);       // h*G + g
    int bn = t >> 6;             // b*N + n
    int b  = bn >> 10;           // /N
    int n  = bn & (NN - 1);

    const float* q = v_in + (size_t)t * 3;
    const float* r = r_in + (size_t)bn * 9;
    float q0 = q[0], q1 = q[1], q2 = q[2];

    // v_i = sum_j r[i][j] * q[j]
    float vx = r[0]*q0 + r[1]*q1 + r[2]*q2;
    float vy = r[3]*q0 + r[4]*q1 + r[5]*q2;
    float vz = r[6]*q0 + r[7]*q1 + r[8]*q2;

    float nrm = sqrtf(vx*vx + vy*vy + vz*vz);
    float inv = 1.0f / fmaxf(nrm, 1e-12f);
    float x = vx*inv, y = vy*inv, z = vz*inv;
    float x2 = x*x, y2 = y*y, z2 = z*z;

    // constants (integral normalization factors folded in, plus "scale")
    const float f1 = 0.4886025119029199f * scale;  // sqrt(3/(4pi))
    const float f2 = 0.6307831305050401f * scale;  // sqrt(5/(4pi))
    const float f3 = 0.7463526651802308f * scale;  // sqrt(7/(4pi))
    const float s3  = 1.7320508075688772f;
    const float s15 = 3.8729833462074170f;
    const float c1  = 0.6123724356957945f;         // sqrt(3/8)
    const float c3  = 0.7905694150420949f;         // sqrt(5/8)

    float Y0  = f1 * x;
    float Y1  = f1 * y;
    float Y2  = f1 * z;

    float Y3  = f2 * (s3 * x * z);
    float Y4  = f2 * (s3 * x * y);
    float Y5  = f2 * (y2 - 0.5f * (x2 + z2));
    float Y6  = f2 * (s3 * y * z);
    float Y7  = f2 * (0.5f * s3) * (z2 - x2);

    float Y8  = f3 * (c3 * x * (3.0f * z2 - x2));
    float Y9  = f3 * (s15 * x * y * z);
    float Y10 = f3 * (c1 * x * (4.0f * y2 - x2 - z2));
    float Y11 = f3 * (0.5f * y * (2.0f * y2 - 3.0f * x2 - 3.0f * z2));
    float Y12 = f3 * (c1 * z * (4.0f * y2 - x2 - z2));
    float Y13 = f3 * (0.5f * s15) * (y * (z2 - x2));
    float Y14 = f3 * (c3 * z * (z2 - 3.0f * x2));

    float* Y = which ? g_Yk : g_Yq;
    size_t obase = (((size_t)b * HG + hg) * NN + n) * DPAD;
    float4* o = (float4*)(Y + obase);
    o[0] = make_float4(Y0,  Y1,  Y2,  Y3);
    o[1] = make_float4(Y4,  Y5,  Y6,  Y7);
    o[2] = make_float4(Y8,  Y9,  Y10, Y11);
    o[3] = make_float4(Y12, Y13, Y14, 0.0f);
}

// ---------------------------------------------------------------------------
// Kernel 2: batched small-K GEMM. scores[batch, n, m] = sum_d Yq[n,d]*Yk[m,d]
// 64x64 output tile per block, 256 threads, 4x4 micro-tile per thread.
// K-major shared tiles avoid strided-row bank conflicts on the A reads.
// ---------------------------------------------------------------------------
__global__ void score_gemm_kernel(float* __restrict__ out)
{
    __shared__ float As[DPAD][64];  // [k][n]
    __shared__ float Bs[DPAD][64];  // [k][m]

    int batch = blockIdx.z;
    int n0 = blockIdx.y * 64;
    int m0 = blockIdx.x * 64;
    int tid = threadIdx.x;

    // Stage tiles: each thread loads one float4 of A and one of B (k-chunk c)
    int row = tid >> 2;          // 0..63
    int c   = tid & 3;           // 0..3  -> k = 4c..4c+3
    const float4* A4 = (const float4*)(g_Yq + (size_t)batch * NN * DPAD);
    const float4* B4 = (const float4*)(g_Yk + (size_t)batch * NN * DPAD);
    float4 va = A4[(size_t)(n0 + row) * 4 + c];
    float4 vb = B4[(size_t)(m0 + row) * 4 + c];
    int kb = c * 4;
    As[kb + 0][row] = va.x; As[kb + 1][row] = va.y;
    As[kb + 2][row] = va.z; As[kb + 3][row] = va.w;
    Bs[kb + 0][row] = vb.x; Bs[kb + 1][row] = vb.y;
    Bs[kb + 2][row] = vb.z; Bs[kb + 3][row] = vb.w;
    __syncthreads();

    int tx = tid & 15;           // m micro-tile (x4)
    int ty = tid >> 4;           // n micro-tile (x4)

    float acc[4][4];
    #pragma unroll
    for (int i = 0; i < 4; i++)
        #pragma unroll
        for (int j = 0; j < 4; j++) acc[i][j] = 0.0f;

    #pragma unroll
    for (int k = 0; k < 15; k++) {
        float a0 = As[k][ty*4 + 0], a1 = As[k][ty*4 + 1];
        float a2 = As[k][ty*4 + 2], a3 = As[k][ty*4 + 3];
        float b0 = Bs[k][tx*4 + 0], b1 = Bs[k][tx*4 + 1];
        float b2 = Bs[k][tx*4 + 2], b3 = Bs[k][tx*4 + 3];
        acc[0][0] += a0*b0; acc[0][1] += a0*b1; acc[0][2] += a0*b2; acc[0][3] += a0*b3;
        acc[1][0] += a1*b0; acc[1][1] += a1*b1; acc[1][2] += a1*b2; acc[1][3] += a1*b3;
        acc[2][0] += a2*b0; acc[2][1] += a2*b1; acc[2][2] += a2*b2; acc[2][3] += a2*b3;
        acc[3][0] += a3*b0; acc[3][1] += a3*b1; acc[3][2] += a3*b2; acc[3][3] += a3*b3;
    }

    float* o = out + (size_t)batch * NN * NN + (size_t)n0 * NN + m0;
    #pragma unroll
    for (int i = 0; i < 4; i++) {
        float4 st = make_float4(acc[i][0], acc[i][1], acc[i][2], acc[i][3]);
        ((float4*)(o + (size_t)(ty*4 + i) * NN))[tx] = st;
    }
}

// ---------------------------------------------------------------------------
extern "C" void kernel_launch(void* const* d_in, const int* in_sizes, int n_in,
                              void* d_out, int out_size)
{
    const float* q  = (const float*)d_in[0];
    const float* k  = (const float*)d_in[1];
    const float* rq = (const float*)d_in[2];
    const float* rk = (const float*)d_in[3];
    float* out = (float*)d_out;

    const float inv_sqrt15 = 0.2581988897471611f;

    int blocks = (NROWS + 255) / 256;
    sh_expand_kernel<<<blocks, 256>>>(q, rq, inv_sqrt15, 0);  // Y_q (scaled)
    sh_expand_kernel<<<blocks, 256>>>(k, rk, 1.0f,       1);  // Y_k

    dim3 grid(NN / 64, NN / 64, NBATCH);  // 16 x 16 x 128
    score_gemm_kernel<<<grid, 256>>>(out);
}